// round 16
// baseline (speedup 1.0000x reference)
#include <cuda_runtime.h>
#include <cuda_fp16.h>
#include <math.h>
#include <stdint.h>

// Problem constants (fixed by the reference)
#define NNODES 20000
#define NEDGES 320000
#define HDIM   512
#define NPAD   20096            // 157 * 128, padded row count for GEMM tiles

// ---------------- scratch (device globals; no runtime allocation) ----------------
__device__ __half   d_s [NNODES * HDIM];       // GEMM output (fp16)
__device__ __half   d_Ah[NPAD * HDIM];         // activation (fp16), padded
__device__ __half   d_Wh[3 * HDIM * HDIM];     // W^T (fp16), [N,K] layout, 3 layers
__device__ int      d_counts[NNODES];
__device__ int      d_rowptr[NNODES + 1];
__device__ int      d_rowoff[NNODES];
__device__ int2     d_epack[NEDGES];       // (col, float-bits(val))
__device__ float    d_g[1024];             // accumulated [max | mean] over 3 layers
__device__ unsigned d_gmax[HDIM];
__device__ float    d_gsum[HDIM];
__device__ unsigned d_poolctr;             // pool completion counter (reset each use)

// ================= PTX helpers (generic compute_103-safe) =================
__device__ __forceinline__ uint32_t smem_u32(const void* p) {
    uint32_t a;
    asm("{ .reg .u64 t; cvta.to.shared.u64 t, %1; cvt.u32.u64 %0, t; }" : "=r"(a) : "l"(p));
    return a;
}
__device__ __forceinline__ void cp_async16(uint32_t dst, const void* src) {
    asm volatile("cp.async.cg.shared.global [%0], [%1], 16;" :: "r"(dst), "l"(src));
}
#define CP_COMMIT() asm volatile("cp.async.commit_group;" ::: "memory")
#define CP_WAIT1()  asm volatile("cp.async.wait_group 1;" ::: "memory")

__device__ __forceinline__ void ldsm_x4(uint32_t* r, uint32_t addr) {
    asm volatile("ldmatrix.sync.aligned.m8n8.x4.shared.b16 {%0,%1,%2,%3}, [%4];"
        : "=r"(r[0]), "=r"(r[1]), "=r"(r[2]), "=r"(r[3]) : "r"(addr));
}
__device__ __forceinline__ void mma_f16(float* c, const uint32_t* a, const uint32_t* b) {
    asm volatile(
        "mma.sync.aligned.m16n8k16.row.col.f32.f16.f16.f32 "
        "{%0,%1,%2,%3}, {%4,%5,%6,%7}, {%8,%9}, {%0,%1,%2,%3};"
        : "+f"(c[0]), "+f"(c[1]), "+f"(c[2]), "+f"(c[3])
        : "r"(a[0]), "r"(a[1]), "r"(a[2]), "r"(a[3]), "r"(b[0]), "r"(b[1]));
}

// ---------------- init: zero counters / accumulators ----------------
__global__ void init_kernel() {
    int i = blockIdx.x * blockDim.x + threadIdx.x;
    if (i < NNODES) d_counts[i] = 0;
    if (i < 1024)   d_g[i] = 0.0f;
    if (i < HDIM) { d_gmax[i] = 0u; d_gsum[i] = 0.0f; }
    if (i == 0)     d_poolctr = 0u;
}

// ---------------- CSR build ----------------
__global__ void hist_kernel(const int* __restrict__ rows) {
    int e = blockIdx.x * blockDim.x + threadIdx.x;
    if (e < NEDGES) atomicAdd(&d_counts[rows[e]], 1);
}

// single-block scan over 20000 counts -> rowptr (+ rowoff copy fused)
__global__ void scan_kernel() {
    __shared__ int sums[1024];
    const int CH = 20;
    int t = threadIdx.x;
    int base = t * CH;
    int local[CH];
    int run = 0;
#pragma unroll
    for (int i = 0; i < CH; i++) {
        int idx = base + i;
        int v = (idx < NNODES) ? d_counts[idx] : 0;
        run += v;
        local[i] = run;
    }
    sums[t] = run;
    __syncthreads();
    for (int off = 1; off < 1024; off <<= 1) {
        int v = 0;
        if (t >= off) v = sums[t - off];
        __syncthreads();
        if (t >= off) sums[t] += v;
        __syncthreads();
    }
    int offset = (t > 0) ? sums[t - 1] : 0;
#pragma unroll
    for (int i = 0; i < CH; i++) {
        int idx = base + i;
        if (idx < NNODES) {
            d_rowptr[idx + 1] = offset + local[i];
            d_rowoff[idx] = (i == 0) ? offset : offset + local[i - 1];
        }
    }
    if (t == 0) d_rowptr[0] = 0;
}

__global__ void scatter_kernel(const int* __restrict__ rows,
                               const int* __restrict__ cols,
                               const float* __restrict__ vals) {
    int e = blockIdx.x * blockDim.x + threadIdx.x;
    if (e < NEDGES) {
        int r = rows[e];
        int p = atomicAdd(&d_rowoff[r], 1);
        d_epack[p] = make_int2(cols[e], __float_as_int(vals[e]));
    }
}

// ---------------- fp32 -> fp16 convert (layer-1 input only) ----------------
__global__ void convert_kernel(const float* __restrict__ src, int n4) {
    int i = blockIdx.x * blockDim.x + threadIdx.x;
    if (i >= n4) return;
    float4 v = ((const float4*)src)[i];
    ((__half2*)d_Ah)[2 * i]     = __floats2half2_rn(v.x, v.y);
    ((__half2*)d_Ah)[2 * i + 1] = __floats2half2_rn(v.z, v.w);
}

// ---------------- W [K,N] -> W^T [N,K] fp16, all 3 layers in one launch ----------------
__global__ void transconv_kernel(const float* __restrict__ W1,
                                 const float* __restrict__ W2,
                                 const float* __restrict__ W3) {
    __shared__ float t[32][33];
    const float* W = (blockIdx.z == 0) ? W1 : (blockIdx.z == 1) ? W2 : W3;
    size_t obase = (size_t)blockIdx.z * HDIM * HDIM;
    int bx = blockIdx.x * 32, by = blockIdx.y * 32;
    int x = threadIdx.x, y = threadIdx.y;   // 32 x 8
#pragma unroll
    for (int j = 0; j < 32; j += 8)
        t[y + j][x] = W[(size_t)(by + y + j) * HDIM + bx + x];
    __syncthreads();
#pragma unroll
    for (int j = 0; j < 32; j += 8) {
        size_t o = obase + (size_t)(bx + y + j) * HDIM + by + x;
        d_Wh[o] = __float2half_rn(t[x][y + j]);
    }
}

// ---------------- HMMA fp16 GEMM: C[M,512] = A @ B^T, fp16 in/out (round-10 best) ----------------
#define TILE_B   16384                 // 128 rows x 64 fp16 x 2B (128B rows)
#define STAGE_B  (2 * TILE_B)          // A, B
#define DYN_SMEM (2 * STAGE_B)         // 65536

__device__ __forceinline__ void load_tile(uint32_t smem_base,
                                          const __half* __restrict__ src,
                                          int row_base, int k0, int tid) {
    int row = tid >> 1;
    int c0  = (tid & 1) * 4;
    const __half* g = src + (size_t)(row_base + row) * HDIM + k0;
    uint32_t sb = smem_base + row * 128;
    int xr = row & 7;
#pragma unroll
    for (int c = c0; c < c0 + 4; ++c)
        cp_async16(sb + ((c ^ xr) << 4), g + c * 8);
}

__global__ __launch_bounds__(256, 2)
void gemm_f16_kernel(const __half* __restrict__ A, const __half* __restrict__ Bh,
                     __half* __restrict__ C, int M) {
    extern __shared__ __align__(1024) char dsm[];

    const int tid  = threadIdx.x;
    const int wid  = tid >> 5;
    const int lane = tid & 31;
    const int warp_m = wid >> 2;     // 0..1
    const int warp_n = wid & 3;      // 0..3
    const int block_row = blockIdx.x * 128;
    const int block_col = blockIdx.y * 128;

    uint32_t s_base = smem_u32(dsm);

    float acc[4][4][4];
#pragma unroll
    for (int i = 0; i < 4; i++)
#pragma unroll
        for (int j = 0; j < 4; j++)
#pragma unroll
            for (int q = 0; q < 4; q++) acc[i][j][q] = 0.0f;

    // prologue: stage 0 (k0=0), stage 1 (k0=64)
    {
        uint32_t st = s_base;
        load_tile(st,          A,  block_row, 0, tid);
        load_tile(st + TILE_B, Bh, block_col, 0, tid);
        CP_COMMIT();
        st = s_base + STAGE_B;
        load_tile(st,          A,  block_row, 64, tid);
        load_tile(st + TILE_B, Bh, block_col, 64, tid);
        CP_COMMIT();
    }

    const int a_row  = warp_m * 64 + (lane & 15);
    const int a_half = lane >> 4;
    const int a_x    = a_row & 7;
    const int b_row  = warp_n * 32 + (lane & 15);
    const int b_half = lane >> 4;
    const int b_x    = b_row & 7;

#pragma unroll 1
    for (int c = 0; c < 8; ++c) {
        CP_WAIT1();
        __syncthreads();
        uint32_t st  = s_base + (uint32_t)(c & 1) * STAGE_B;
        uint32_t sA  = st;
        uint32_t sBh = st + TILE_B;

#pragma unroll
        for (int kk = 0; kk < 4; ++kk) {
            uint32_t a_chunk_off = (uint32_t)(((2 * kk + a_half) ^ a_x) << 4);
            uint32_t b_chunk_off = (uint32_t)(((2 * kk + b_half) ^ b_x) << 4);
            uint32_t ah[4][4];
#pragma unroll
            for (int i = 0; i < 4; ++i) {
                uint32_t ro = (uint32_t)(a_row + i * 16) * 128 + a_chunk_off;
                ldsm_x4(ah[i], sA + ro);
            }
            uint32_t bh[4][2];
#pragma unroll
            for (int p = 0; p < 2; ++p) {
                uint32_t ro = (uint32_t)(b_row + p * 16) * 128 + b_chunk_off;
                uint32_t r[4];
                ldsm_x4(r, sBh + ro);
                bh[2 * p][0] = r[0]; bh[2 * p][1] = r[2];
                bh[2 * p + 1][0] = r[1]; bh[2 * p + 1][1] = r[3];
            }
#pragma unroll
            for (int i = 0; i < 4; ++i)
#pragma unroll
                for (int j = 0; j < 4; ++j)
                    mma_f16(acc[i][j], ah[i], bh[j]);
        }
        __syncthreads();
        if (c + 2 < 8) {
            uint32_t st2 = s_base + (uint32_t)(c & 1) * STAGE_B;
            int k0 = (c + 2) * 64;
            load_tile(st2,          A,  block_row, k0, tid);
            load_tile(st2 + TILE_B, Bh, block_col, k0, tid);
        }
        CP_COMMIT();
    }

    // epilogue: fp16 stores
    const int r_in = lane >> 2;
    const int c_in = (lane & 3) * 2;
#pragma unroll
    for (int i = 0; i < 4; ++i) {
        int row0 = block_row + warp_m * 64 + i * 16 + r_in;
#pragma unroll
        for (int j = 0; j < 4; ++j) {
            int col = block_col + warp_n * 32 + j * 8 + c_in;
            if (row0 < M)
                *(__half2*)(C + (size_t)row0 * HDIM + col) =
                    __floats2half2_rn(acc[i][j][0], acc[i][j][1]);
            if (row0 + 8 < M)
                *(__half2*)(C + (size_t)(row0 + 8) * HDIM + col) =
                    __floats2half2_rn(acc[i][j][2], acc[i][j][3]);
        }
    }
}

// ---------------- CSR SpMM: 4 rows/block, 64 threads/row, 16B gathers ----------------
__global__ __launch_bounds__(256)
void spmm_relu_kernel(const float* __restrict__ bias) {
    int r  = blockIdx.x * 4 + (threadIdx.x >> 6);
    int tr = threadIdx.x & 63;               // 0..63, owns 8 fp16 features
    int beg = d_rowptr[r];
    int end = d_rowptr[r + 1];
    float acc[8];
#pragma unroll
    for (int q = 0; q < 8; ++q) acc[q] = 0.0f;

    const size_t foff = (size_t)tr * 8;
    int j = beg;
    for (; j + 1 < end; j += 2) {
        int2 e0 = d_epack[j], e1 = d_epack[j + 1];
        uint4 g0 = *(const uint4*)(d_s + (size_t)e0.x * HDIM + foff);
        uint4 g1 = *(const uint4*)(d_s + (size_t)e1.x * HDIM + foff);
        float v0 = __int_as_float(e0.y), v1 = __int_as_float(e1.y);
        float2 p0 = __half22float2(*(__half2*)&g0.x), p1 = __half22float2(*(__half2*)&g0.y);
        float2 p2 = __half22float2(*(__half2*)&g0.z), p3 = __half22float2(*(__half2*)&g0.w);
        acc[0] = fmaf(v0, p0.x, acc[0]); acc[1] = fmaf(v0, p0.y, acc[1]);
        acc[2] = fmaf(v0, p1.x, acc[2]); acc[3] = fmaf(v0, p1.y, acc[3]);
        acc[4] = fmaf(v0, p2.x, acc[4]); acc[5] = fmaf(v0, p2.y, acc[5]);
        acc[6] = fmaf(v0, p3.x, acc[6]); acc[7] = fmaf(v0, p3.y, acc[7]);
        float2 q0 = __half22float2(*(__half2*)&g1.x), q1 = __half22float2(*(__half2*)&g1.y);
        float2 q2 = __half22float2(*(__half2*)&g1.z), q3 = __half22float2(*(__half2*)&g1.w);
        acc[0] = fmaf(v1, q0.x, acc[0]); acc[1] = fmaf(v1, q0.y, acc[1]);
        acc[2] = fmaf(v1, q1.x, acc[2]); acc[3] = fmaf(v1, q1.y, acc[3]);
        acc[4] = fmaf(v1, q2.x, acc[4]); acc[5] = fmaf(v1, q2.y, acc[5]);
        acc[6] = fmaf(v1, q3.x, acc[6]); acc[7] = fmaf(v1, q3.y, acc[7]);
    }
    if (j < end) {
        int2 e0 = d_epack[j];
        uint4 g0 = *(const uint4*)(d_s + (size_t)e0.x * HDIM + foff);
        float v0 = __int_as_float(e0.y);
        float2 p0 = __half22float2(*(__half2*)&g0.x), p1 = __half22float2(*(__half2*)&g0.y);
        float2 p2 = __half22float2(*(__half2*)&g0.z), p3 = __half22float2(*(__half2*)&g0.w);
        acc[0] = fmaf(v0, p0.x, acc[0]); acc[1] = fmaf(v0, p0.y, acc[1]);
        acc[2] = fmaf(v0, p1.x, acc[2]); acc[3] = fmaf(v0, p1.y, acc[3]);
        acc[4] = fmaf(v0, p2.x, acc[4]); acc[5] = fmaf(v0, p2.y, acc[5]);
        acc[6] = fmaf(v0, p3.x, acc[6]); acc[7] = fmaf(v0, p3.y, acc[7]);
    }
    float4 b0 = *(const float4*)(bias + foff);
    float4 b1 = *(const float4*)(bias + foff + 4);
    float h0 = fmaxf(acc[0] + b0.x, 0.f), h1 = fmaxf(acc[1] + b0.y, 0.f);
    float h2 = fmaxf(acc[2] + b0.z, 0.f), h3 = fmaxf(acc[3] + b0.w, 0.f);
    float h4 = fmaxf(acc[4] + b1.x, 0.f), h5 = fmaxf(acc[5] + b1.y, 0.f);
    float h6 = fmaxf(acc[6] + b1.z, 0.f), h7 = fmaxf(acc[7] + b1.w, 0.f);
    __half2 o0 = __floats2half2_rn(h0, h1);
    __half2 o1 = __floats2half2_rn(h2, h3);
    __half2 o2 = __floats2half2_rn(h4, h5);
    __half2 o3 = __floats2half2_rn(h6, h7);
    uint4 ov;
    ov.x = *(uint32_t*)&o0; ov.y = *(uint32_t*)&o1;
    ov.z = *(uint32_t*)&o2; ov.w = *(uint32_t*)&o3;
    *(uint4*)(d_Ah + (size_t)r * HDIM + foff) = ov;
}

// ---------------- pooling + fused combine; last layer also runs the head inline ----------------
// grid = 148 blocks (one wave), 256 threads
__global__ __launch_bounds__(256)
void pool_kernel(int do_head,
                 const float* __restrict__ l1W, const float* __restrict__ l1b,
                 const float* __restrict__ l2W, const float* __restrict__ l2b,
                 const float* __restrict__ l3W, const float* __restrict__ l3b,
                 float* __restrict__ out) {
    int f2 = threadIdx.x;               // feature pair 0..255
    const __half2* H = (const __half2*)d_Ah;
    float mx0 = 0.f, mx1 = 0.f, sm0 = 0.f, sm1 = 0.f;
    for (int n = blockIdx.x; n < NNODES; n += gridDim.x) {
        __half2 h = H[(size_t)n * 256 + f2];
        float v0 = __half2float(h.x);
        float v1 = __half2float(h.y);
        mx0 = fmaxf(mx0, v0); sm0 += v0;
        mx1 = fmaxf(mx1, v1); sm1 += v1;
    }
    atomicMax(&d_gmax[2 * f2],     __float_as_uint(mx0));   // valid: values >= 0
    atomicMax(&d_gmax[2 * f2 + 1], __float_as_uint(mx1));
    atomicAdd(&d_gsum[2 * f2],     sm0);
    atomicAdd(&d_gsum[2 * f2 + 1], sm1);

    // last-arriving block: fold into d_g (and optionally run the MLP head)
    __shared__ bool is_last;
    __threadfence();
    if (threadIdx.x == 0)
        is_last = (atomicAdd(&d_poolctr, 1u) == gridDim.x - 1);
    __syncthreads();
    if (!is_last) return;

    {
        int f = threadIdx.x;
#pragma unroll
        for (int q = 0; q < 2; ++q, f += 256) {
            d_g[f]       += __uint_as_float(d_gmax[f]);
            d_g[512 + f] += d_gsum[f] * (1.0f / (float)NNODES);
            d_gmax[f] = 0u;
            d_gsum[f] = 0.0f;
        }
        if (threadIdx.x == 0) d_poolctr = 0u;
    }
    if (!do_head) return;

    // ---- inline MLP head + log_softmax (reads d_g written by this block) ----
    __syncthreads();
    __shared__ float y1[128];
    __shared__ float y2[64];
    __shared__ float y3[10];
    int t = threadIdx.x;
    if (t < 128) {
        float acc = 0.0f;
        for (int i = 0; i < 1024; i++)
            acc = fmaf(d_g[i], l1W[i * 128 + t], acc);
        y1[t] = fmaxf(acc + l1b[t], 0.0f);
    }
    __syncthreads();
    if (t < 64) {
        float acc = 0.0f;
#pragma unroll 8
        for (int i = 0; i < 128; i++)
            acc = fmaf(y1[i], l2W[i * 64 + t], acc);
        y2[t] = fmaxf(acc + l2b[t], 0.0f);
    }
    __syncthreads();
    if (t < 10) {
        float acc = 0.0f;
#pragma unroll
        for (int i = 0; i < 64; i++)
            acc = fmaf(y2[i], l3W[i * 10 + t], acc);
        y3[t] = acc + l3b[t];
    }
    __syncthreads();
    if (t == 0) {
        float m = -1e30f;
#pragma unroll
        for (int j = 0; j < 10; j++) m = fmaxf(m, y3[j]);
        float s = 0.0f;
#pragma unroll
        for (int j = 0; j < 10; j++) s += expf(y3[j] - m);
        float lse = m + logf(s);
#pragma unroll
        for (int j = 0; j < 10; j++) out[j] = y3[j] - lse;
    }
}

// ---------------- launch (round-10 topology; head fused into pool(2)) ----------------
extern "C" void kernel_launch(void* const* d_in, const int* in_sizes, int n_in,
                              void* d_out, int out_size) {
    const float* x        = (const float*)d_in[0];
    const int*   rows     = (const int*)  d_in[1];
    const int*   cols     = (const int*)  d_in[2];
    const float* adj_vals = (const float*)d_in[3];
    const float* W1 = (const float*)d_in[4];
    const float* b1 = (const float*)d_in[5];
    const float* W2 = (const float*)d_in[6];
    const float* b2 = (const float*)d_in[7];
    const float* W3 = (const float*)d_in[8];
    const float* b3 = (const float*)d_in[9];
    const float* l1W = (const float*)d_in[10];
    const float* l1b = (const float*)d_in[11];
    const float* l2W = (const float*)d_in[12];
    const float* l2b = (const float*)d_in[13];
    const float* l3W = (const float*)d_in[14];
    const float* l3b = (const float*)d_in[15];
    float* out = (float*)d_out;

    __half *s_g, *Ah_g, *Wh_g;
    cudaGetSymbolAddress((void**)&s_g,  d_s);
    cudaGetSymbolAddress((void**)&Ah_g, d_Ah);
    cudaGetSymbolAddress((void**)&Wh_g, d_Wh);

    static bool once = false;
    static cudaStream_t sCSR, sPool;
    static cudaEvent_t evFork, evW, evCSR, evSpmm[3], evPool[3], evDone;
    if (!once) {
        cudaFuncSetAttribute(gemm_f16_kernel,
                             cudaFuncAttributeMaxDynamicSharedMemorySize, DYN_SMEM);
        cudaStreamCreateWithFlags(&sCSR,  cudaStreamNonBlocking);
        cudaStreamCreateWithFlags(&sPool, cudaStreamNonBlocking);
        cudaEventCreateWithFlags(&evFork, cudaEventDisableTiming);
        cudaEventCreateWithFlags(&evW,    cudaEventDisableTiming);
        cudaEventCreateWithFlags(&evCSR,  cudaEventDisableTiming);
        cudaEventCreateWithFlags(&evDone, cudaEventDisableTiming);
        for (int i = 0; i < 3; i++) {
            cudaEventCreateWithFlags(&evSpmm[i], cudaEventDisableTiming);
            cudaEventCreateWithFlags(&evPool[i], cudaEventDisableTiming);
        }
        once = true;
    }

    const size_t WOFF = (size_t)HDIM * HDIM;
    const float* bb[3] = {b1, b2, b3};
    cudaStream_t s0 = 0;

    // fork side streams from capture stream
    cudaEventRecord(evFork, s0);
    cudaStreamWaitEvent(sCSR, evFork, 0);
    cudaStreamWaitEvent(sPool, evFork, 0);

    dim3 gemm_grid((NNODES + 127) / 128, HDIM / 128);   // (157, 4)

    // side stream: weight transpose (parallel with convert), then CSR build
    transconv_kernel<<<dim3(16, 16, 3), dim3(32, 8), 0, sCSR>>>(W1, W2, W3);
    cudaEventRecord(evW, sCSR);
    init_kernel<<<(NNODES + 255) / 256, 256, 0, sCSR>>>();
    hist_kernel<<<(NEDGES + 255) / 256, 256, 0, sCSR>>>(rows);
    scan_kernel<<<1, 1024, 0, sCSR>>>();
    scatter_kernel<<<(NEDGES + 255) / 256, 256, 0, sCSR>>>(rows, cols, adj_vals);
    cudaEventRecord(evCSR, sCSR);

    // main stream: layer-1 input conversion, then GEMM1 (waits for W)
    convert_kernel<<<(NNODES * HDIM / 4 + 255) / 256, 256, 0, s0>>>(x, NNODES * HDIM / 4);
    cudaStreamWaitEvent(s0, evW, 0);
    gemm_f16_kernel<<<gemm_grid, 256, DYN_SMEM, s0>>>(Ah_g, Wh_g, s_g, NNODES);

    for (int L = 0; L < 3; ++L) {
        if (L > 0)
            gemm_f16_kernel<<<gemm_grid, 256, DYN_SMEM, s0>>>(
                Ah_g, Wh_g + L * WOFF, s_g, NNODES);
        if (L == 0) cudaStreamWaitEvent(s0, evCSR, 0);          // CSR ready before SpMM1
        else        cudaStreamWaitEvent(s0, evPool[L - 1], 0);  // pool(L-1) done reading d_Ah
        spmm_relu_kernel<<<NNODES / 4, 256, 0, s0>>>(bb[L]);
        cudaEventRecord(evSpmm[L], s0);

        // pool (+fused combine; layer 2 also runs the head) on side stream
        cudaStreamWaitEvent(sPool, evSpmm[L], 0);
        pool_kernel<<<148, 256, 0, sPool>>>((L == 2) ? 1 : 0,
                                            l1W, l1b, l2W, l2b, l3W, l3b, out);
        cudaEventRecord(evPool[L], sPool);
    }

    // join: ensure out is written before capture end (head ran inside pool(2))
    cudaEventRecord(evDone, sPool);
    cudaStreamWaitEvent(s0, evDone, 0);
}

// round 17
// speedup vs baseline: 1.0958x; 1.0958x over previous
#include <cuda_runtime.h>
#include <cuda_fp16.h>
#include <math.h>
#include <stdint.h>

// Problem constants (fixed by the reference)
#define NNODES 20000
#define NEDGES 320000
#define HDIM   512
#define NPAD   20096            // 157 * 128, padded row count for GEMM tiles

// ---------------- scratch (device globals; no runtime allocation) ----------------
__device__ __half   d_s [NNODES * HDIM];       // GEMM output (fp16)
__device__ __half   d_Ah[NPAD * HDIM];         // activation (fp16), padded
__device__ __half   d_Wh[3 * HDIM * HDIM];     // W^T (fp16), [N,K] layout, 3 layers
__device__ int      d_counts[NNODES];
__device__ int      d_rowptr[NNODES + 1];
__device__ int      d_rowoff[NNODES];
__device__ int2     d_epack[NEDGES];       // (col, float-bits(val))
__device__ float    d_g[1024];             // accumulated [max | mean] over 3 layers
__device__ unsigned d_gmax[HDIM];
__device__ float    d_gsum[HDIM];
__device__ unsigned d_poolctr;             // pool completion counter (reset each use)

// ================= PTX helpers (generic compute_103-safe) =================
__device__ __forceinline__ uint32_t smem_u32(const void* p) {
    uint32_t a;
    asm("{ .reg .u64 t; cvta.to.shared.u64 t, %1; cvt.u32.u64 %0, t; }" : "=r"(a) : "l"(p));
    return a;
}
__device__ __forceinline__ void cp_async16(uint32_t dst, const void* src) {
    asm volatile("cp.async.cg.shared.global [%0], [%1], 16;" :: "r"(dst), "l"(src));
}
#define CP_COMMIT() asm volatile("cp.async.commit_group;" ::: "memory")
#define CP_WAIT1()  asm volatile("cp.async.wait_group 1;" ::: "memory")

__device__ __forceinline__ void ldsm_x4(uint32_t* r, uint32_t addr) {
    asm volatile("ldmatrix.sync.aligned.m8n8.x4.shared.b16 {%0,%1,%2,%3}, [%4];"
        : "=r"(r[0]), "=r"(r[1]), "=r"(r[2]), "=r"(r[3]) : "r"(addr));
}
__device__ __forceinline__ void mma_f16(float* c, const uint32_t* a, const uint32_t* b) {
    asm volatile(
        "mma.sync.aligned.m16n8k16.row.col.f32.f16.f16.f32 "
        "{%0,%1,%2,%3}, {%4,%5,%6,%7}, {%8,%9}, {%0,%1,%2,%3};"
        : "+f"(c[0]), "+f"(c[1]), "+f"(c[2]), "+f"(c[3])
        : "r"(a[0]), "r"(a[1]), "r"(a[2]), "r"(a[3]), "r"(b[0]), "r"(b[1]));
}

// ---------------- init: zero counters / accumulators ----------------
__global__ void init_kernel() {
    int i = blockIdx.x * blockDim.x + threadIdx.x;
    if (i < NNODES) d_counts[i] = 0;
    if (i < 1024)   d_g[i] = 0.0f;
    if (i < HDIM) { d_gmax[i] = 0u; d_gsum[i] = 0.0f; }
    if (i == 0)     d_poolctr = 0u;
}

// ---------------- CSR build ----------------
__global__ void hist_kernel(const int* __restrict__ rows) {
    int e = blockIdx.x * blockDim.x + threadIdx.x;
    if (e < NEDGES) atomicAdd(&d_counts[rows[e]], 1);
}

// single-block scan over 20000 counts -> rowptr (+ rowoff copy fused)
__global__ void scan_kernel() {
    __shared__ int sums[1024];
    const int CH = 20;
    int t = threadIdx.x;
    int base = t * CH;
    int local[CH];
    int run = 0;
#pragma unroll
    for (int i = 0; i < CH; i++) {
        int idx = base + i;
        int v = (idx < NNODES) ? d_counts[idx] : 0;
        run += v;
        local[i] = run;
    }
    sums[t] = run;
    __syncthreads();
    for (int off = 1; off < 1024; off <<= 1) {
        int v = 0;
        if (t >= off) v = sums[t - off];
        __syncthreads();
        if (t >= off) sums[t] += v;
        __syncthreads();
    }
    int offset = (t > 0) ? sums[t - 1] : 0;
#pragma unroll
    for (int i = 0; i < CH; i++) {
        int idx = base + i;
        if (idx < NNODES) {
            d_rowptr[idx + 1] = offset + local[i];
            d_rowoff[idx] = (i == 0) ? offset : offset + local[i - 1];
        }
    }
    if (t == 0) d_rowptr[0] = 0;
}

__global__ void scatter_kernel(const int* __restrict__ rows,
                               const int* __restrict__ cols,
                               const float* __restrict__ vals) {
    int e = blockIdx.x * blockDim.x + threadIdx.x;
    if (e < NEDGES) {
        int r = rows[e];
        int p = atomicAdd(&d_rowoff[r], 1);
        d_epack[p] = make_int2(cols[e], __float_as_int(vals[e]));
    }
}

// ---------------- fp32 -> fp16 convert (layer-1 input only) ----------------
__global__ void convert_kernel(const float* __restrict__ src, int n4) {
    int i = blockIdx.x * blockDim.x + threadIdx.x;
    if (i >= n4) return;
    float4 v = ((const float4*)src)[i];
    ((__half2*)d_Ah)[2 * i]     = __floats2half2_rn(v.x, v.y);
    ((__half2*)d_Ah)[2 * i + 1] = __floats2half2_rn(v.z, v.w);
}

// ---------------- W [K,N] -> W^T [N,K] fp16, all 3 layers in one launch ----------------
__global__ void transconv_kernel(const float* __restrict__ W1,
                                 const float* __restrict__ W2,
                                 const float* __restrict__ W3) {
    __shared__ float t[32][33];
    const float* W = (blockIdx.z == 0) ? W1 : (blockIdx.z == 1) ? W2 : W3;
    size_t obase = (size_t)blockIdx.z * HDIM * HDIM;
    int bx = blockIdx.x * 32, by = blockIdx.y * 32;
    int x = threadIdx.x, y = threadIdx.y;   // 32 x 8
#pragma unroll
    for (int j = 0; j < 32; j += 8)
        t[y + j][x] = W[(size_t)(by + y + j) * HDIM + bx + x];
    __syncthreads();
#pragma unroll
    for (int j = 0; j < 32; j += 8) {
        size_t o = obase + (size_t)(bx + y + j) * HDIM + by + x;
        d_Wh[o] = __float2half_rn(t[x][y + j]);
    }
}

// ---------------- HMMA fp16 GEMM: C[M,512] = A @ B^T, fp16 in/out ----------------
// Block tile 128x128, BK=64, 2-stage cp.async double buffer, 8 warps (2x4), warp tile 64x32.
#define TILE_B   16384                 // 128 rows x 64 fp16 x 2B (128B rows)
#define STAGE_B  (2 * TILE_B)          // A, B
#define DYN_SMEM (2 * STAGE_B)         // 65536

__device__ __forceinline__ void load_tile(uint32_t smem_base,
                                          const __half* __restrict__ src,
                                          int row_base, int k0, int tid) {
    int row = tid >> 1;
    int c0  = (tid & 1) * 4;
    const __half* g = src + (size_t)(row_base + row) * HDIM + k0;
    uint32_t sb = smem_base + row * 128;
    int xr = row & 7;
#pragma unroll
    for (int c = c0; c < c0 + 4; ++c)
        cp_async16(sb + ((c ^ xr) << 4), g + c * 8);
}

__global__ __launch_bounds__(256, 2)
void gemm_f16_kernel(const __half* __restrict__ A, const __half* __restrict__ Bh,
                     __half* __restrict__ C, int M) {
    extern __shared__ __align__(1024) char dsm[];

    const int tid  = threadIdx.x;
    const int wid  = tid >> 5;
    const int lane = tid & 31;
    const int warp_m = wid >> 2;     // 0..1
    const int warp_n = wid & 3;      // 0..3
    const int block_row = blockIdx.x * 128;
    const int block_col = blockIdx.y * 128;

    uint32_t s_base = smem_u32(dsm);

    float acc[4][4][4];
#pragma unroll
    for (int i = 0; i < 4; i++)
#pragma unroll
        for (int j = 0; j < 4; j++)
#pragma unroll
            for (int q = 0; q < 4; q++) acc[i][j][q] = 0.0f;

    // prologue: stage 0 (k0=0), stage 1 (k0=64)
    {
        uint32_t st = s_base;
        load_tile(st,          A,  block_row, 0, tid);
        load_tile(st + TILE_B, Bh, block_col, 0, tid);
        CP_COMMIT();
        st = s_base + STAGE_B;
        load_tile(st,          A,  block_row, 64, tid);
        load_tile(st + TILE_B, Bh, block_col, 64, tid);
        CP_COMMIT();
    }

    const int a_row  = warp_m * 64 + (lane & 15);
    const int a_half = lane >> 4;
    const int a_x    = a_row & 7;
    const int b_row  = warp_n * 32 + (lane & 15);
    const int b_half = lane >> 4;
    const int b_x    = b_row & 7;

#pragma unroll 1
    for (int c = 0; c < 8; ++c) {
        CP_WAIT1();
        __syncthreads();
        uint32_t st  = s_base + (uint32_t)(c & 1) * STAGE_B;
        uint32_t sA  = st;
        uint32_t sBh = st + TILE_B;

#pragma unroll
        for (int kk = 0; kk < 4; ++kk) {
            uint32_t a_chunk_off = (uint32_t)(((2 * kk + a_half) ^ a_x) << 4);
            uint32_t b_chunk_off = (uint32_t)(((2 * kk + b_half) ^ b_x) << 4);
            uint32_t ah[4][4];
#pragma unroll
            for (int i = 0; i < 4; ++i) {
                uint32_t ro = (uint32_t)(a_row + i * 16) * 128 + a_chunk_off;
                ldsm_x4(ah[i], sA + ro);
            }
            uint32_t bh[4][2];
#pragma unroll
            for (int p = 0; p < 2; ++p) {
                uint32_t ro = (uint32_t)(b_row + p * 16) * 128 + b_chunk_off;
                uint32_t r[4];
                ldsm_x4(r, sBh + ro);
                bh[2 * p][0] = r[0]; bh[2 * p][1] = r[2];
                bh[2 * p + 1][0] = r[1]; bh[2 * p + 1][1] = r[3];
            }
#pragma unroll
            for (int i = 0; i < 4; ++i)
#pragma unroll
                for (int j = 0; j < 4; ++j)
                    mma_f16(acc[i][j], ah[i], bh[j]);
        }
        __syncthreads();
        if (c + 2 < 8) {
            uint32_t st2 = s_base + (uint32_t)(c & 1) * STAGE_B;
            int k0 = (c + 2) * 64;
            load_tile(st2,          A,  block_row, k0, tid);
            load_tile(st2 + TILE_B, Bh, block_col, k0, tid);
        }
        CP_COMMIT();
    }

    // epilogue: fp16 stores
    const int r_in = lane >> 2;
    const int c_in = (lane & 3) * 2;
#pragma unroll
    for (int i = 0; i < 4; ++i) {
        int row0 = block_row + warp_m * 64 + i * 16 + r_in;
#pragma unroll
        for (int j = 0; j < 4; ++j) {
            int col = block_col + warp_n * 32 + j * 8 + c_in;
            if (row0 < M)
                *(__half2*)(C + (size_t)row0 * HDIM + col) =
                    __floats2half2_rn(acc[i][j][0], acc[i][j][1]);
            if (row0 + 8 < M)
                *(__half2*)(C + (size_t)(row0 + 8) * HDIM + col) =
                    __floats2half2_rn(acc[i][j][2], acc[i][j][3]);
        }
    }
}

// ---------------- CSR SpMM: 2 rows/block, 64 threads/row, 16B gathers ----------------
__global__ __launch_bounds__(128)
void spmm_relu_kernel(const float* __restrict__ bias) {
    int r  = blockIdx.x * 2 + (threadIdx.x >> 6);
    int tr = threadIdx.x & 63;               // 0..63, owns 8 fp16 features
    int beg = d_rowptr[r];
    int end = d_rowptr[r + 1];
    float acc[8];
#pragma unroll
    for (int q = 0; q < 8; ++q) acc[q] = 0.0f;

    const size_t foff = (size_t)tr * 8;
    int j = beg;
    for (; j + 1 < end; j += 2) {
        int2 e0 = d_epack[j], e1 = d_epack[j + 1];
        uint4 g0 = *(const uint4*)(d_s + (size_t)e0.x * HDIM + foff);
        uint4 g1 = *(const uint4*)(d_s + (size_t)e1.x * HDIM + foff);
        float v0 = __int_as_float(e0.y), v1 = __int_as_float(e1.y);
        float2 p0 = __half22float2(*(__half2*)&g0.x), p1 = __half22float2(*(__half2*)&g0.y);
        float2 p2 = __half22float2(*(__half2*)&g0.z), p3 = __half22float2(*(__half2*)&g0.w);
        acc[0] = fmaf(v0, p0.x, acc[0]); acc[1] = fmaf(v0, p0.y, acc[1]);
        acc[2] = fmaf(v0, p1.x, acc[2]); acc[3] = fmaf(v0, p1.y, acc[3]);
        acc[4] = fmaf(v0, p2.x, acc[4]); acc[5] = fmaf(v0, p2.y, acc[5]);
        acc[6] = fmaf(v0, p3.x, acc[6]); acc[7] = fmaf(v0, p3.y, acc[7]);
        float2 q0 = __half22float2(*(__half2*)&g1.x), q1 = __half22float2(*(__half2*)&g1.y);
        float2 q2 = __half22float2(*(__half2*)&g1.z), q3 = __half22float2(*(__half2*)&g1.w);
        acc[0] = fmaf(v1, q0.x, acc[0]); acc[1] = fmaf(v1, q0.y, acc[1]);
        acc[2] = fmaf(v1, q1.x, acc[2]); acc[3] = fmaf(v1, q1.y, acc[3]);
        acc[4] = fmaf(v1, q2.x, acc[4]); acc[5] = fmaf(v1, q2.y, acc[5]);
        acc[6] = fmaf(v1, q3.x, acc[6]); acc[7] = fmaf(v1, q3.y, acc[7]);
    }
    if (j < end) {
        int2 e0 = d_epack[j];
        uint4 g0 = *(const uint4*)(d_s + (size_t)e0.x * HDIM + foff);
        float v0 = __int_as_float(e0.y);
        float2 p0 = __half22float2(*(__half2*)&g0.x), p1 = __half22float2(*(__half2*)&g0.y);
        float2 p2 = __half22float2(*(__half2*)&g0.z), p3 = __half22float2(*(__half2*)&g0.w);
        acc[0] = fmaf(v0, p0.x, acc[0]); acc[1] = fmaf(v0, p0.y, acc[1]);
        acc[2] = fmaf(v0, p1.x, acc[2]); acc[3] = fmaf(v0, p1.y, acc[3]);
        acc[4] = fmaf(v0, p2.x, acc[4]); acc[5] = fmaf(v0, p2.y, acc[5]);
        acc[6] = fmaf(v0, p3.x, acc[6]); acc[7] = fmaf(v0, p3.y, acc[7]);
    }
    float4 b0 = *(const float4*)(bias + foff);
    float4 b1 = *(const float4*)(bias + foff + 4);
    float h0 = fmaxf(acc[0] + b0.x, 0.f), h1 = fmaxf(acc[1] + b0.y, 0.f);
    float h2 = fmaxf(acc[2] + b0.z, 0.f), h3 = fmaxf(acc[3] + b0.w, 0.f);
    float h4 = fmaxf(acc[4] + b1.x, 0.f), h5 = fmaxf(acc[5] + b1.y, 0.f);
    float h6 = fmaxf(acc[6] + b1.z, 0.f), h7 = fmaxf(acc[7] + b1.w, 0.f);
    __half2 o0 = __floats2half2_rn(h0, h1);
    __half2 o1 = __floats2half2_rn(h2, h3);
    __half2 o2 = __floats2half2_rn(h4, h5);
    __half2 o3 = __floats2half2_rn(h6, h7);
    uint4 ov;
    ov.x = *(uint32_t*)&o0; ov.y = *(uint32_t*)&o1;
    ov.z = *(uint32_t*)&o2; ov.w = *(uint32_t*)&o3;
    *(uint4*)(d_Ah + (size_t)r * HDIM + foff) = ov;
}

// ---------------- pooling (fp16 activation) + fused combine in last block ----------------
__global__ __launch_bounds__(256)
void pool_kernel() {
    int f2 = threadIdx.x;               // feature pair 0..255
    const __half2* H = (const __half2*)d_Ah;
    float mx0 = 0.f, mx1 = 0.f, sm0 = 0.f, sm1 = 0.f;
    for (int n = blockIdx.x; n < NNODES; n += gridDim.x) {
        __half2 h = H[(size_t)n * 256 + f2];
        float v0 = __half2float(h.x);
        float v1 = __half2float(h.y);
        mx0 = fmaxf(mx0, v0); sm0 += v0;
        mx1 = fmaxf(mx1, v1); sm1 += v1;
    }
    atomicMax(&d_gmax[2 * f2],     __float_as_uint(mx0));   // valid: values >= 0
    atomicMax(&d_gmax[2 * f2 + 1], __float_as_uint(mx1));
    atomicAdd(&d_gsum[2 * f2],     sm0);
    atomicAdd(&d_gsum[2 * f2 + 1], sm1);

    __shared__ bool is_last;
    __threadfence();
    if (threadIdx.x == 0)
        is_last = (atomicAdd(&d_poolctr, 1u) == gridDim.x - 1);
    __syncthreads();
    if (is_last) {
        int f = threadIdx.x;
#pragma unroll
        for (int q = 0; q < 2; ++q, f += 256) {
            d_g[f]       += __uint_as_float(d_gmax[f]);
            d_g[512 + f] += d_gsum[f] * (1.0f / (float)NNODES);
            d_gmax[f] = 0u;
            d_gsum[f] = 0.0f;
        }
        if (threadIdx.x == 0) d_poolctr = 0u;
    }
}

// ---------------- MLP head + log_softmax ----------------
__global__ __launch_bounds__(128)
void head_kernel(const float* __restrict__ l1W, const float* __restrict__ l1b,
                 const float* __restrict__ l2W, const float* __restrict__ l2b,
                 const float* __restrict__ l3W, const float* __restrict__ l3b,
                 float* __restrict__ out) {
    __shared__ float y1[128];
    __shared__ float y2[64];
    __shared__ float y3[10];
    int t = threadIdx.x;
    {
        float acc = 0.0f;
        for (int i = 0; i < 1024; i++)
            acc = fmaf(d_g[i], l1W[i * 128 + t], acc);
        y1[t] = fmaxf(acc + l1b[t], 0.0f);
    }
    __syncthreads();
    if (t < 64) {
        float acc = 0.0f;
#pragma unroll 8
        for (int i = 0; i < 128; i++)
            acc = fmaf(y1[i], l2W[i * 64 + t], acc);
        y2[t] = fmaxf(acc + l2b[t], 0.0f);
    }
    __syncthreads();
    if (t < 10) {
        float acc = 0.0f;
#pragma unroll
        for (int i = 0; i < 64; i++)
            acc = fmaf(y2[i], l3W[i * 10 + t], acc);
        y3[t] = acc + l3b[t];
    }
    __syncthreads();
    if (t == 0) {
        float m = -1e30f;
#pragma unroll
        for (int j = 0; j < 10; j++) m = fmaxf(m, y3[j]);
        float s = 0.0f;
#pragma unroll
        for (int j = 0; j < 10; j++) s += expf(y3[j] - m);
        float lse = m + logf(s);
#pragma unroll
        for (int j = 0; j < 10; j++) out[j] = y3[j] - lse;
    }
}

// ---------------- launch (round-10 best-measured topology) ----------------
extern "C" void kernel_launch(void* const* d_in, const int* in_sizes, int n_in,
                              void* d_out, int out_size) {
    const float* x        = (const float*)d_in[0];
    const int*   rows     = (const int*)  d_in[1];
    const int*   cols     = (const int*)  d_in[2];
    const float* adj_vals = (const float*)d_in[3];
    const float* W1 = (const float*)d_in[4];
    const float* b1 = (const float*)d_in[5];
    const float* W2 = (const float*)d_in[6];
    const float* b2 = (const float*)d_in[7];
    const float* W3 = (const float*)d_in[8];
    const float* b3 = (const float*)d_in[9];
    const float* l1W = (const float*)d_in[10];
    const float* l1b = (const float*)d_in[11];
    const float* l2W = (const float*)d_in[12];
    const float* l2b = (const float*)d_in[13];
    const float* l3W = (const float*)d_in[14];
    const float* l3b = (const float*)d_in[15];
    float* out = (float*)d_out;

    __half *s_g, *Ah_g, *Wh_g;
    cudaGetSymbolAddress((void**)&s_g,  d_s);
    cudaGetSymbolAddress((void**)&Ah_g, d_Ah);
    cudaGetSymbolAddress((void**)&Wh_g, d_Wh);

    static bool once = false;
    static cudaStream_t sCSR, sPool;
    static cudaEvent_t evFork, evW, evCSR, evSpmm[3], evPool[3], evDone;
    if (!once) {
        cudaFuncSetAttribute(gemm_f16_kernel,
                             cudaFuncAttributeMaxDynamicSharedMemorySize, DYN_SMEM);
        cudaStreamCreateWithFlags(&sCSR,  cudaStreamNonBlocking);
        cudaStreamCreateWithFlags(&sPool, cudaStreamNonBlocking);
        cudaEventCreateWithFlags(&evFork, cudaEventDisableTiming);
        cudaEventCreateWithFlags(&evW,    cudaEventDisableTiming);
        cudaEventCreateWithFlags(&evCSR,  cudaEventDisableTiming);
        cudaEventCreateWithFlags(&evDone, cudaEventDisableTiming);
        for (int i = 0; i < 3; i++) {
            cudaEventCreateWithFlags(&evSpmm[i], cudaEventDisableTiming);
            cudaEventCreateWithFlags(&evPool[i], cudaEventDisableTiming);
        }
        once = true;
    }

    const size_t WOFF = (size_t)HDIM * HDIM;
    const float* bb[3] = {b1, b2, b3};
    cudaStream_t s0 = 0;

    // fork side streams from capture stream
    cudaEventRecord(evFork, s0);
    cudaStreamWaitEvent(sCSR, evFork, 0);
    cudaStreamWaitEvent(sPool, evFork, 0);

    dim3 gemm_grid((NNODES + 127) / 128, HDIM / 128);   // (157, 4)

    // side stream: weight transpose (parallel with convert), then CSR build
    transconv_kernel<<<dim3(16, 16, 3), dim3(32, 8), 0, sCSR>>>(W1, W2, W3);
    cudaEventRecord(evW, sCSR);
    init_kernel<<<(NNODES + 255) / 256, 256, 0, sCSR>>>();
    hist_kernel<<<(NEDGES + 255) / 256, 256, 0, sCSR>>>(rows);
    scan_kernel<<<1, 1024, 0, sCSR>>>();
    scatter_kernel<<<(NEDGES + 255) / 256, 256, 0, sCSR>>>(rows, cols, adj_vals);
    cudaEventRecord(evCSR, sCSR);

    // main stream: layer-1 input conversion, then GEMM1 (waits for W)
    convert_kernel<<<(NNODES * HDIM / 4 + 255) / 256, 256, 0, s0>>>(x, NNODES * HDIM / 4);
    cudaStreamWaitEvent(s0, evW, 0);
    gemm_f16_kernel<<<gemm_grid, 256, DYN_SMEM, s0>>>(Ah_g, Wh_g, s_g, NNODES);

    for (int L = 0; L < 3; ++L) {
        if (L > 0)
            gemm_f16_kernel<<<gemm_grid, 256, DYN_SMEM, s0>>>(
                Ah_g, Wh_g + L * WOFF, s_g, NNODES);
        if (L == 0) cudaStreamWaitEvent(s0, evCSR, 0);          // CSR ready before SpMM1
        else        cudaStreamWaitEvent(s0, evPool[L - 1], 0);  // pool(L-1) done reading d_Ah
        spmm_relu_kernel<<<NNODES / 2, 128, 0, s0>>>(bb[L]);
        cudaEventRecord(evSpmm[L], s0);

        // pool (+fused combine) on side stream, overlapped with next GEMM
        cudaStreamWaitEvent(sPool, evSpmm[L], 0);
        pool_kernel<<<256, 256, 0, sPool>>>();
        cudaEventRecord(evPool[L], sPool);
    }

    // join: head needs pool3's fused combine (d_g complete)
    cudaEventRecord(evDone, sPool);
    cudaStreamWaitEvent(s0, evDone, 0);
    head_kernel<<<1, 128, 0, s0>>>(l1W, l1b, l2W, l2b, l3W, l3b, out);
}